// round 17
// baseline (speedup 1.0000x reference)
#include <cuda_runtime.h>
#include <cuda_bf16.h>
#include <math.h>
#include <stdint.h>

#define NN    100000
#define EE    1600000
#define CC    128
#define FIN   64
#define NSTEP 4
#define NEG_SLOPE 0.01f

// ---------------- scratch (static device globals) ----------------
// interleaved h state: per node 32 uint4 blocks; block b = channels 4b..4b+3:
//   {hh01, hh23, hl01, hl23}
__device__ __align__(256) uint4 g_h2a[(size_t)NN * 32], g_h2b[(size_t)NN * 32];
__device__ __align__(256) uint4 g_a2[(size_t)NN * 32];                  // interleaved agg
__device__ __align__(256) __nv_bfloat16 g_xh[(size_t)NN * FIN], g_xl[(size_t)NN * FIN];
__device__ __align__(256) __nv_bfloat16 g_Bemb_h[CC * FIN], g_Bemb_l[CC * FIN];
__device__ __align__(256) float g_W1[NSTEP][384 * 128];
__device__ __align__(256) __nv_bfloat16 g_Bg_h[NSTEP][512 * 256];
__device__ __align__(256) __nv_bfloat16 g_Bg_l[NSTEP][512 * 256];
__device__ int   g_deg[NN];
__device__ int   g_rowstart[NN + 1];
__device__ int   g_cursor[NN];
__device__ int   g_csrsrc[EE];
__device__ int   g_blocksum[128];
__device__ int   g_blockoff[128];
__device__ int   g_is64;
__device__ float g_colsum[CC];

// ---------------- helpers ----------------
__device__ __forceinline__ uint32_t smem_u32(const void* p) {
    uint32_t a;
    asm("{ .reg .u64 t; cvta.to.shared.u64 t, %1; cvt.u32.u64 %0, t; }" : "=r"(a) : "l"(p));
    return a;
}
__device__ __forceinline__ void cp16(uint32_t dst, const void* src, int sz) {
    asm volatile("cp.async.cg.shared.global [%0], [%1], 16, %2;"
                 :: "r"(dst), "l"(src), "r"(sz));
}
__device__ __forceinline__ void cp8(uint32_t dst, const void* src, int sz) {
    asm volatile("cp.async.ca.shared.global [%0], [%1], 8, %2;"
                 :: "r"(dst), "l"(src), "r"(sz));
}
#define CP_COMMIT() asm volatile("cp.async.commit_group;" ::: "memory")
#define CP_WAIT0()  asm volatile("cp.async.wait_group 0;" ::: "memory")

#define LDSM_X4(r0, r1, r2, r3, addr)                                        \
    asm volatile("ldmatrix.sync.aligned.m8n8.x4.shared.b16 {%0,%1,%2,%3}, [%4];" \
                 : "=r"(r0), "=r"(r1), "=r"(r2), "=r"(r3) : "r"(addr))

__device__ __forceinline__ void mma_bf16(float* d, const uint32_t* a, const uint32_t* b) {
    asm volatile(
        "mma.sync.aligned.m16n8k16.row.col.f32.bf16.bf16.f32 "
        "{%0,%1,%2,%3}, {%4,%5,%6,%7}, {%8,%9}, {%0,%1,%2,%3};"
        : "+f"(d[0]), "+f"(d[1]), "+f"(d[2]), "+f"(d[3])
        : "r"(a[0]), "r"(a[1]), "r"(a[2]), "r"(a[3]), "r"(b[0]), "r"(b[1]));
}
__device__ __forceinline__ void split1(float v, __nv_bfloat16& hi, __nv_bfloat16& lo) {
    hi = __float2bfloat16(v);
    lo = __float2bfloat16(v - __bfloat162float(hi));
}
__device__ __forceinline__ float2 bf2_to_f2(uint32_t u) {
    __nv_bfloat162 t = *reinterpret_cast<__nv_bfloat162*>(&u);
    return make_float2(__bfloat162float(t.x), __bfloat162float(t.y));
}
__device__ __forceinline__ uint32_t packbf2(__nv_bfloat16 a, __nv_bfloat16 b) {
    __nv_bfloat162 t; t.x = a; t.y = b;
    return *reinterpret_cast<uint32_t*>(&t);
}

// ---------------- edge dtype detection ----------------
__global__ void detect_k(const void* __restrict__ edges) {
    if (threadIdx.x == 0 && blockIdx.x == 0) {
        const long long* p = (const long long*)edges;
        int is64 = 1;
        for (int i = 0; i < 256; i++) {
            long long v = p[i];
            if (v < 0 || v >= (long long)NN) { is64 = 0; break; }
        }
        g_is64 = is64;
    }
}
__device__ __forceinline__ int edge_at(const void* edges, int which, int e, bool is64) {
    if (is64) return (int)((const long long*)edges)[(size_t)which * EE + e];
    return ((const int*)edges)[(size_t)which * EE + e];
}

// ---------------- CSR build ----------------
__global__ void zero_deg_k() {
    for (int i = blockIdx.x * blockDim.x + threadIdx.x; i < NN; i += gridDim.x * blockDim.x)
        g_deg[i] = 0;
}
__global__ void hist_k(const void* __restrict__ edges) {
    bool is64 = g_is64;
    for (int e = blockIdx.x * blockDim.x + threadIdx.x; e < EE; e += gridDim.x * blockDim.x)
        atomicAdd(&g_deg[edge_at(edges, 1, e, is64)], 1);
}
__global__ void scan1_k() {
    __shared__ int s[1024];
    int tid = threadIdx.x;
    int i = blockIdx.x * 1024 + tid;
    int v = (i < NN) ? g_deg[i] : 0;
    s[tid] = v;
    __syncthreads();
    for (int off = 1; off < 1024; off <<= 1) {
        int t = (tid >= off) ? s[tid - off] : 0;
        __syncthreads();
        s[tid] += t;
        __syncthreads();
    }
    if (i < NN) g_rowstart[i] = s[tid] - v;
    if (tid == 1023) g_blocksum[blockIdx.x] = s[1023];
}
__global__ void scan2_k(int nb) {
    if (threadIdx.x == 0 && blockIdx.x == 0) {
        int acc = 0;
        for (int b = 0; b < nb; b++) { int t = g_blocksum[b]; g_blockoff[b] = acc; acc += t; }
        g_rowstart[NN] = acc;
    }
}
__global__ void scan3_k() {
    int i = blockIdx.x * 1024 + threadIdx.x;
    if (i < NN) {
        int v = g_rowstart[i] + g_blockoff[blockIdx.x];
        g_rowstart[i] = v;
        g_cursor[i] = v;
    }
}
__global__ void scatter_k(const void* __restrict__ edges) {
    bool is64 = g_is64;
    for (int e = blockIdx.x * blockDim.x + threadIdx.x; e < EE; e += gridDim.x * blockDim.x) {
        int src = edge_at(edges, 0, e, is64);
        int dst = edge_at(edges, 1, e, is64);
        g_csrsrc[atomicAdd(&g_cursor[dst], 1)] = src;
    }
}

// ---------------- operand / weight prep ----------------
__global__ void convert_x_k(const float* __restrict__ x) {
    int i = blockIdx.x * blockDim.x + threadIdx.x;
    if (i >= NN * FIN) return;
    split1(x[i], g_xh[i], g_xl[i]);
}
__global__ void pack_emb_k(const float* __restrict__ Win) {
    int i = blockIdx.x * blockDim.x + threadIdx.x;
    if (i >= CC * FIN) return;
    split1(Win[i], g_Bemb_h[i], g_Bemb_l[i]);
}
__global__ void w1_k(const float* __restrict__ Wm, const float* __restrict__ Wih, int step) {
    int i = blockIdx.x * blockDim.x + threadIdx.x;
    if (i >= 384 * 128) return;
    int n = i >> 7, k = i & 127;
    const float* wm = Wm + k * 128;
    const float* wi = Wih + n * 128;
    float s = 0.f;
#pragma unroll 8
    for (int j = 0; j < 128; ++j) s = fmaf(wm[j], wi[j], s);
    g_W1[step][i] = s;
}
// R7 layout: row n' -> (y=n'>>7, gate=(n'>>5)&3, cl=n'&31, channel c=y*32+cl)
__global__ void pack_gru_k(const float* __restrict__ Whh, int step) {
    int i = blockIdx.x * blockDim.x + threadIdx.x;
    if (i >= 512 * 256) return;
    int np = i >> 8, k = i & 255;
    int y = np >> 7, gate = (np >> 5) & 3, cl = np & 31;
    int c = y * 32 + cl;
    float v;
    if (gate < 3) {
        int lr = gate * 128 + c;
        v = (k < 128) ? g_W1[step][lr * 128 + k] : Whh[lr * 128 + (k - 128)];
    } else {
        v = (k < 128) ? 0.f : Whh[(256 + c) * 128 + (k - 128)];
    }
    split1(v, g_Bg_h[step][i], g_Bg_l[step][i]);
}

// ================= embed gemm (BM=128, K=64) -> interleaved h =================
#define ST 20
#define STG_WORDS (4 * 128 * ST)
#define EMB_SMEM (2 * STG_WORDS * 4)

__global__ void __launch_bounds__(256, 2) tc_gemm_embed(
    const __nv_bfloat16* __restrict__ Ah, const __nv_bfloat16* __restrict__ Al,
    const __nv_bfloat16* __restrict__ Bh, const __nv_bfloat16* __restrict__ Bl,
    uint4* __restrict__ h2out, int M)
{
    extern __shared__ uint32_t dsm[];
    const uint32_t sbase = smem_u32(dsm);
    const int tid = threadIdx.x, lane = tid & 31, warp = tid >> 5;
    const int wr = warp & 1, wc = warp >> 1, g = lane >> 2, t = lane & 3;
    const int q = lane >> 3, rq = lane & 7;
    const int row0 = blockIdx.x * 128;

    float acc[4][4][4];
#pragma unroll
    for (int i = 0; i < 4; i++)
#pragma unroll
        for (int j = 0; j < 4; j++)
#pragma unroll
            for (int k = 0; k < 4; k++) acc[i][j][k] = 0.f;

    auto load_stage = [&](int buf, int kt) {
        const uint32_t stg = sbase + (uint32_t)buf * STG_WORDS * 4;
#pragma unroll
        for (int it = 0; it < 8; ++it) {
            int idx = tid + it * 256;
            int arr = idx >> 9, rem = idx & 511;
            int r = rem >> 2, c16 = rem & 3;
            int gk = kt + c16 * 8;
            uint32_t dst = stg + (uint32_t)(arr * 128 * ST + r * ST + c16 * 4) * 4;
            const __nv_bfloat16* src;
            int sz = 16;
            if (arr < 2) {
                int grow = row0 + r;
                int srow = (grow < M) ? grow : 0;
                if (grow >= M) sz = 0;
                src = (arr == 0 ? Ah : Al) + (size_t)srow * FIN + gk;
            } else {
                src = (arr == 2 ? Bh : Bl) + (size_t)r * FIN + gk;
            }
            cp16(dst, src, sz);
        }
    };

    load_stage(0, 0);
    CP_COMMIT();
    for (int ch = 0; ch < 2; ++ch) {
        CP_WAIT0();
        __syncthreads();
        if (ch == 0) { load_stage(1, 32); CP_COMMIT(); }
        const uint32_t S = sbase + (uint32_t)(ch & 1) * STG_WORDS * 4;
        const uint32_t sAH = S, sAL = S + 128 * ST * 4;
        const uint32_t sBH = S + 2 * 128 * ST * 4, sBL = S + 3 * 128 * ST * 4;
#pragma unroll
        for (int kk2 = 0; kk2 < 2; ++kk2) {
            const int kw = kk2 * 8;
            uint32_t bh[4][2], bl[4][2];
            int brow = (q >> 1) * 8 + rq;
            int bword = kw + (q & 1) * 4;
#pragma unroll
            for (int ntp = 0; ntp < 2; ++ntp) {
                int n0 = wc * 32 + ntp * 16;
                uint32_t off = (uint32_t)((n0 + brow) * ST + bword) * 4;
                LDSM_X4(bh[ntp * 2][0], bh[ntp * 2][1],
                        bh[ntp * 2 + 1][0], bh[ntp * 2 + 1][1], sBH + off);
                LDSM_X4(bl[ntp * 2][0], bl[ntp * 2][1],
                        bl[ntp * 2 + 1][0], bl[ntp * 2 + 1][1], sBL + off);
            }
            int arow = (q & 1) * 8 + rq;
            int aword = kw + (q >> 1) * 4;
#pragma unroll
            for (int mt = 0; mt < 4; mt++) {
                int m0 = wr * 64 + mt * 16;
                uint32_t off = (uint32_t)((m0 + arow) * ST + aword) * 4;
                uint32_t ah[4], al[4];
                LDSM_X4(ah[0], ah[1], ah[2], ah[3], sAH + off);
                LDSM_X4(al[0], al[1], al[2], al[3], sAL + off);
#pragma unroll
                for (int nt = 0; nt < 4; nt++) {
                    mma_bf16(acc[mt][nt], ah, bh[nt]);
                    mma_bf16(acc[mt][nt], ah, bl[nt]);
                    mma_bf16(acc[mt][nt], al, bh[nt]);
                }
            }
        }
        __syncthreads();
    }

    uint32_t* o32 = reinterpret_cast<uint32_t*>(h2out);
#pragma unroll
    for (int mt = 0; mt < 4; mt++) {
        int rbase = row0 + wr * 64 + mt * 16 + g;
#pragma unroll
        for (int nt = 0; nt < 4; nt++) {
            int col = wc * 32 + nt * 8 + 2 * t;      // even
#pragma unroll
            for (int half = 0; half < 2; ++half) {
                int rr = rbase + half * 8;
                if (rr >= M) continue;
                float v0 = acc[mt][nt][half * 2], v1 = acc[mt][nt][half * 2 + 1];
                __nv_bfloat16 h0, l0, h1, l1;
                split1(v0, h0, l0); split1(v1, h1, l1);
                size_t bw = (size_t)rr * 128 + (col >> 2) * 4 + ((col >> 1) & 1);
                o32[bw]     = packbf2(h0, h1);
                o32[bw + 2] = packbf2(l0, l1);
            }
        }
    }
}

// ================= A-resident GRU gemm, BM=64, 2 CTA/SM (champion R7, interleaved A src) ====
#define A_ST   132
#define AOFF_LO 8448
#define WB     16896
#define BSTG   5120
#define GRU_SMEM (27136 * 4)

__global__ void __launch_bounds__(256, 2) tc_gemm_gru(
    const uint4* __restrict__ a2, const uint4* __restrict__ h2_in,
    const __nv_bfloat16* __restrict__ Bh,  const __nv_bfloat16* __restrict__ Bl,
    uint4* __restrict__ h2_out,
    const float* __restrict__ bih, const float* __restrict__ bhh,
    int M)
{
    extern __shared__ uint32_t dsm[];
    const uint32_t sbase = smem_u32(dsm);
    const int tid = threadIdx.x, lane = tid & 31, warp = tid >> 5;
    const int wr = warp & 1, wc = warp >> 1, g = lane >> 2, t = lane & 3;
    const int q = lane >> 3, rq = lane & 7;
    const int cl = tid & 31;
    const int row0 = blockIdx.x * 64;

    // ---- load A tile once: 64 rows x 256 k, hi+lo (8B cp.async from interleaved) ----
    const char* a2b = (const char*)a2;
    const char* h2b = (const char*)h2_in;
#pragma unroll
    for (int it = 0; it < 32; ++it) {
        int idx = tid + it * 256;            // 0..8191
        int arr = idx >> 12;                 // 0=hi 1=lo
        int rem = idx & 4095;
        int r = rem >> 6, b = rem & 63;      // b<32: agg block; b>=32: h block (k0 = 4b)
        uint32_t dst = sbase + (uint32_t)((arr ? AOFF_LO : 0) + r * A_ST + (b << 1)) * 4;
        int grow = row0 + r;
        int srow = (grow < M) ? grow : 0;
        int sz = (grow < M) ? 8 : 0;
        const char* src = (b < 32 ? a2b : h2b) + (size_t)srow * 512 + (size_t)(b & 31) * 16
                          + (arr ? 8 : 0);
        cp8(dst, src, sz);
    }
    CP_COMMIT();

    auto load_B = [&](int s, int y, int ch) {
        const uint32_t stg = sbase + (uint32_t)(WB + s * BSTG) * 4;
#pragma unroll
        for (int it = 0; it < 4; ++it) {
            int idx = tid + it * 256;
            int arr = idx >> 9;
            int rem = idx & 511;
            int r = rem >> 2, c16 = rem & 3;
            uint32_t dst = stg + (uint32_t)(arr * 2560 + r * ST + c16 * 4) * 4;
            const __nv_bfloat16* src =
                (arr ? Bl : Bh) + (size_t)(y * 128 + r) * 256 + ch * 32 + c16 * 8;
            cp16(dst, src, 16);
        }
    };

    const uint32_t sAH = sbase, sAL = sbase + AOFF_LO * 4;
    float* stageF = reinterpret_cast<float*>(dsm + WB);

    for (int y = 0; y < 4; ++y) {
        float acc[2][4][4];
#pragma unroll
        for (int i = 0; i < 2; i++)
#pragma unroll
            for (int j = 0; j < 4; j++)
#pragma unroll
                for (int k = 0; k < 4; k++) acc[i][j][k] = 0.f;

        load_B(0, y, 0);
        CP_COMMIT();

        for (int ch = 0; ch < 8; ++ch) {
            CP_WAIT0();
            __syncthreads();
            if (ch + 1 < 8) { load_B((ch + 1) & 1, y, ch + 1); CP_COMMIT(); }

            const uint32_t sB = sbase + (uint32_t)(WB + (ch & 1) * BSTG) * 4;
            const uint32_t sBH = sB, sBL = sB + 2560 * 4;
#pragma unroll
            for (int kk2 = 0; kk2 < 2; ++kk2) {
                const int kw = kk2 * 8;
                uint32_t bh[4][2], bl[4][2];
                int brow = (q >> 1) * 8 + rq;
                int bword = kw + (q & 1) * 4;
#pragma unroll
                for (int ntp = 0; ntp < 2; ++ntp) {
                    int n0 = wc * 32 + ntp * 16;
                    uint32_t off = (uint32_t)((n0 + brow) * ST + bword) * 4;
                    LDSM_X4(bh[ntp * 2][0], bh[ntp * 2][1],
                            bh[ntp * 2 + 1][0], bh[ntp * 2 + 1][1], sBH + off);
                    LDSM_X4(bl[ntp * 2][0], bl[ntp * 2][1],
                            bl[ntp * 2 + 1][0], bl[ntp * 2 + 1][1], sBL + off);
                }
                int arow = (q & 1) * 8 + rq;
                int aword = ch * 16 + kw + (q >> 1) * 4;
#pragma unroll
                for (int mt = 0; mt < 2; mt++) {
                    int m0 = wr * 32 + mt * 16;
                    uint32_t off = (uint32_t)((m0 + arow) * A_ST + aword) * 4;
                    uint32_t ah[4], al[4];
                    LDSM_X4(ah[0], ah[1], ah[2], ah[3], sAH + off);
                    LDSM_X4(al[0], al[1], al[2], al[3], sAL + off);
#pragma unroll
                    for (int nt = 0; nt < 4; nt++) {
                        mma_bf16(acc[mt][nt], ah, bh[nt]);
                        mma_bf16(acc[mt][nt], ah, bl[nt]);
                        mma_bf16(acc[mt][nt], al, bh[nt]);
                    }
                }
            }
            __syncthreads();
        }

        // ---- epilogue: acc -> stage (reuses B smem) ----
#pragma unroll
        for (int mt = 0; mt < 2; mt++) {
            int r0 = wr * 32 + mt * 16 + g;
#pragma unroll
            for (int nt = 0; nt < 4; nt++) {
                int col = wc * 32 + nt * 8 + 2 * t;
                *reinterpret_cast<float2*>(&stageF[r0 * A_ST + col]) =
                    make_float2(acc[mt][nt][0], acc[mt][nt][1]);
                *reinterpret_cast<float2*>(&stageF[(r0 + 8) * A_ST + col]) =
                    make_float2(acc[mt][nt][2], acc[mt][nt][3]);
            }
        }
        __syncthreads();

        // ---- fused gates: tile cols {0..31}=r, {32..63}=z, {64..95}=n, {96..127}=Hn ----
        {
            int c = y * 32 + cl;
            float b1r = bih[c] + bhh[c];
            float b1z = bih[CC + c] + bhh[CC + c];
            float bin = bih[2 * CC + c];
            float bhn = bhh[2 * CC + c];
            __nv_bfloat16* outb = reinterpret_cast<__nv_bfloat16*>(h2_out);
#pragma unroll
            for (int it = 0; it < 8; ++it) {
                int idx = tid + it * 256;
                int row = idx >> 5;
                int grow = row0 + row;
                if (grow >= M) continue;
                const float* sr = &stageF[row * A_ST];
                float Gr = sr[cl], Gz = sr[32 + cl], Gn = sr[64 + cl], Hn = sr[96 + cl];
                // old h from A smem tile (k = 128 + c -> AH/AL word 64 + c/2)
                int aw = row * A_ST + 64 + (c >> 1);
                float2 hh2 = bf2_to_f2(dsm[aw]);
                float2 hl2 = bf2_to_f2(dsm[AOFF_LO + aw]);
                float ho = (c & 1) ? (hh2.y + hl2.y) : (hh2.x + hl2.x);
                float r = 1.f / (1.f + expf(-(Gr + b1r)));
                float z = 1.f / (1.f + expf(-(Gz + b1z)));
                float nn = tanhf((Gn - Hn) + bin + r * (Hn + bhn));
                float hnew = (1.f - z) * nn + z * ho;
                __nv_bfloat16 hi, lo;
                split1(hnew, hi, lo);
                size_t b16 = (size_t)grow * 256 + (c >> 2) * 8 + (c & 3);
                outb[b16]     = hi;
                outb[b16 + 4] = lo;
            }
        }
        __syncthreads();
    }
}

// ---------------- aggregation: interleaved gather (1 x 16B LDG per lane-edge) ----------------
__global__ void aggregate_k(const uint4* __restrict__ h2_in) {
    int warp = (blockIdx.x * blockDim.x + threadIdx.x) >> 5;
    int lane = threadIdx.x & 31;
    if (warp >= NN) return;
    int s = g_rowstart[warp], e = g_rowstart[warp + 1];
    float4 acc = make_float4(0.f, 0.f, 0.f, 0.f);
    int i = s;
    for (; i + 4 <= e; i += 4) {
        int s0 = g_csrsrc[i], s1 = g_csrsrc[i + 1], s2 = g_csrsrc[i + 2], s3 = g_csrsrc[i + 3];
        uint4 v0 = h2_in[(size_t)s0 * 32 + lane];
        uint4 v1 = h2_in[(size_t)s1 * 32 + lane];
        uint4 v2 = h2_in[(size_t)s2 * 32 + lane];
        uint4 v3 = h2_in[(size_t)s3 * 32 + lane];
        float2 a0, a1, b0, b1;
        a0 = bf2_to_f2(v0.x); a1 = bf2_to_f2(v0.y); b0 = bf2_to_f2(v0.z); b1 = bf2_to_f2(v0.w);
        acc.x += a0.x + b0.x; acc.y += a0.y + b0.y; acc.z += a1.x + b1.x; acc.w += a1.y + b1.y;
        a0 = bf2_to_f2(v1.x); a1 = bf2_to_f2(v1.y); b0 = bf2_to_f2(v1.z); b1 = bf2_to_f2(v1.w);
        acc.x += a0.x + b0.x; acc.y += a0.y + b0.y; acc.z += a1.x + b1.x; acc.w += a1.y + b1.y;
        a0 = bf2_to_f2(v2.x); a1 = bf2_to_f2(v2.y); b0 = bf2_to_f2(v2.z); b1 = bf2_to_f2(v2.w);
        acc.x += a0.x + b0.x; acc.y += a0.y + b0.y; acc.z += a1.x + b1.x; acc.w += a1.y + b1.y;
        a0 = bf2_to_f2(v3.x); a1 = bf2_to_f2(v3.y); b0 = bf2_to_f2(v3.z); b1 = bf2_to_f2(v3.w);
        acc.x += a0.x + b0.x; acc.y += a0.y + b0.y; acc.z += a1.x + b1.x; acc.w += a1.y + b1.y;
    }
    for (; i < e; ++i) {
        uint4 v = h2_in[(size_t)g_csrsrc[i] * 32 + lane];
        float2 a0 = bf2_to_f2(v.x), a1 = bf2_to_f2(v.y);
        float2 b0 = bf2_to_f2(v.z), b1 = bf2_to_f2(v.w);
        acc.x += a0.x + b0.x; acc.y += a0.y + b0.y;
        acc.z += a1.x + b1.x; acc.w += a1.y + b1.y;
    }
    __nv_bfloat16 h0, l0, h1, l1, h2, l2, h3, l3;
    split1(acc.x, h0, l0); split1(acc.y, h1, l1);
    split1(acc.z, h2, l2); split1(acc.w, h3, l3);
    uint4 outv;
    outv.x = packbf2(h0, h1);
    outv.y = packbf2(h2, h3);
    outv.z = packbf2(l0, l1);
    outv.w = packbf2(l2, l3);
    g_a2[(size_t)warp * 32 + lane] = outv;
}

// ---------------- readout ----------------
__global__ void zero_colsum_k() { if (threadIdx.x < CC) g_colsum[threadIdx.x] = 0.f; }

__global__ void reduce_cols_k(const uint4* __restrict__ h2) {
    int c = threadIdx.x;
    const uint32_t* h32 = reinterpret_cast<const uint32_t*>(h2);
    float acc = 0.f;
    for (int n = blockIdx.x; n < NN; n += gridDim.x) {
        size_t bw = (size_t)n * 128 + (c >> 2) * 4 + ((c >> 1) & 1);
        float2 hv = bf2_to_f2(h32[bw]);
        float2 lv = bf2_to_f2(h32[bw + 2]);
        float v = (c & 1) ? (hv.y + lv.y) : (hv.x + lv.x);
        acc += (v >= 0.f) ? v : NEG_SLOPE * v;
    }
    atomicAdd(&g_colsum[c], acc);
}

__global__ void finalize_k(const float* __restrict__ wpred, const float* __restrict__ bpred,
                           float* __restrict__ out) {
    int lane = threadIdx.x;
    float s = 0.f;
    for (int c = lane; c < CC; c += 32) s += g_colsum[c] * wpred[c];
    for (int o = 16; o; o >>= 1) s += __shfl_xor_sync(0xFFFFFFFFu, s, o);
    if (lane == 0) out[0] = s * (1.0f / (float)NN) + bpred[0];
}

// ---------------- launch ----------------
extern "C" void kernel_launch(void* const* d_in, const int* in_sizes, int n_in,
                              void* d_out, int out_size) {
    const float* x      = (const float*)d_in[0];
    const void*  edges  = d_in[1];
    const float* W_in   = (const float*)d_in[2];
    const float* W_mpnn = (const float*)d_in[3];
    const float* W_ih   = (const float*)d_in[4];
    const float* W_hh   = (const float*)d_in[5];
    const float* b_ih   = (const float*)d_in[6];
    const float* b_hh   = (const float*)d_in[7];
    const float* W_pred = (const float*)d_in[8];
    const float* b_pred = (const float*)d_in[9];
    float* out = (float*)d_out;

    void *p_h2a, *p_h2b, *p_a2, *p_xh, *p_xl, *p_Beh, *p_Bel, *p_Bgh, *p_Bgl;
    cudaGetSymbolAddress(&p_h2a, g_h2a); cudaGetSymbolAddress(&p_h2b, g_h2b);
    cudaGetSymbolAddress(&p_a2, g_a2);
    cudaGetSymbolAddress(&p_xh, g_xh);   cudaGetSymbolAddress(&p_xl, g_xl);
    cudaGetSymbolAddress(&p_Beh, g_Bemb_h); cudaGetSymbolAddress(&p_Bel, g_Bemb_l);
    cudaGetSymbolAddress(&p_Bgh, g_Bg_h);   cudaGetSymbolAddress(&p_Bgl, g_Bg_l);

    uint4* h2buf[2] = { (uint4*)p_h2a, (uint4*)p_h2b };
    uint4* a2 = (uint4*)p_a2;
    __nv_bfloat16 *xh = (__nv_bfloat16*)p_xh, *xl = (__nv_bfloat16*)p_xl;
    __nv_bfloat16 *Beh = (__nv_bfloat16*)p_Beh, *Bel = (__nv_bfloat16*)p_Bel;
    __nv_bfloat16 *Bgh0 = (__nv_bfloat16*)p_Bgh, *Bgl0 = (__nv_bfloat16*)p_Bgl;

    cudaFuncSetAttribute(tc_gemm_embed, cudaFuncAttributeMaxDynamicSharedMemorySize, EMB_SMEM);
    cudaFuncSetAttribute(tc_gemm_gru,   cudaFuncAttributeMaxDynamicSharedMemorySize, GRU_SMEM);

    const int NB = (NN + 1023) / 1024;

    // CSR build
    detect_k<<<1, 32>>>(edges);
    zero_deg_k<<<128, 256>>>();
    hist_k<<<512, 256>>>(edges);
    scan1_k<<<NB, 1024>>>();
    scan2_k<<<1, 32>>>(NB);
    scan3_k<<<NB, 1024>>>();
    scatter_k<<<512, 256>>>(edges);

    // operand prep
    convert_x_k<<<(NN * FIN + 255) / 256, 256>>>(x);
    pack_emb_k<<<(CC * FIN + 255) / 256, 256>>>(W_in);
    for (int s = 0; s < NSTEP; ++s) {
        w1_k<<<(384 * 128 + 255) / 256, 256>>>(W_mpnn + (size_t)s * CC * CC, W_ih, s);
        pack_gru_k<<<(512 * 256 + 255) / 256, 256>>>(W_hh, s);
    }

    dim3 gridE((NN + 127) / 128, 1);
    dim3 gridG((NN + 63) / 64, 1);

    tc_gemm_embed<<<gridE, 256, EMB_SMEM>>>(xh, xl, Beh, Bel, h2buf[0], NN);

    int cur = 0;
    for (int step = 0; step < NSTEP; ++step) {
        aggregate_k<<<NN / 8, 256>>>(h2buf[cur]);

        __nv_bfloat16* Bgh = Bgh0 + (size_t)step * 512 * 256;
        __nv_bfloat16* Bgl = Bgl0 + (size_t)step * 512 * 256;
        tc_gemm_gru<<<gridG, 256, GRU_SMEM>>>(a2, h2buf[cur],
                                              Bgh, Bgl,
                                              h2buf[1 - cur],
                                              b_ih, b_hh, NN);
        cur = 1 - cur;
    }

    zero_colsum_k<<<1, 128>>>();
    reduce_cols_k<<<2048, 128>>>(h2buf[cur]);
    finalize_k<<<1, 32>>>(W_pred, b_pred, out);
}